// round 1
// baseline (speedup 1.0000x reference)
#include <cuda_runtime.h>

// PIF integrate-and-fire, closed form:
//   v0 = x + 0.5f
//   spikes = #{t in [0,8): v0 - t >= 1.0}  ==  clamp(floor(v0), 0, 8)
// (repeated -1.0f subtractions in the reference are exact in fp32 over the
// relevant range, so the closed form is bit-identical to the scan)
//
// Pure HBM-bound elementwise pass: 205.5 MB in + 205.5 MB out.

__global__ void __launch_bounds__(256) pif_kernel(const float4* __restrict__ x,
                                                  float4* __restrict__ out,
                                                  int n4) {
    int i = blockIdx.x * blockDim.x + threadIdx.x;
    if (i < n4) {
        float4 v = x[i];
        float4 r;
        r.x = fminf(fmaxf(floorf(v.x + 0.5f), 0.0f), 8.0f);
        r.y = fminf(fmaxf(floorf(v.y + 0.5f), 0.0f), 8.0f);
        r.z = fminf(fmaxf(floorf(v.z + 0.5f), 0.0f), 8.0f);
        r.w = fminf(fmaxf(floorf(v.w + 0.5f), 0.0f), 8.0f);
        out[i] = r;
    }
}

// Tail handler for element counts not divisible by 4 (not expected here, but safe).
__global__ void pif_tail_kernel(const float* __restrict__ x,
                                float* __restrict__ out,
                                int start, int n) {
    int i = start + blockIdx.x * blockDim.x + threadIdx.x;
    if (i < n) {
        out[i] = fminf(fmaxf(floorf(x[i] + 0.5f), 0.0f), 8.0f);
    }
}

extern "C" void kernel_launch(void* const* d_in, const int* in_sizes, int n_in,
                              void* d_out, int out_size) {
    const float* x = (const float*)d_in[0];
    float* out = (float*)d_out;
    int n = in_sizes[0];

    int n4 = n / 4;
    if (n4 > 0) {
        int threads = 256;
        int blocks = (n4 + threads - 1) / threads;
        pif_kernel<<<blocks, threads>>>((const float4*)x, (float4*)out, n4);
    }
    int rem_start = n4 * 4;
    if (rem_start < n) {
        int rem = n - rem_start;
        pif_tail_kernel<<<(rem + 255) / 256, 256>>>(x, out, rem_start, rem);
    }
}

// round 2
// speedup vs baseline: 1.0327x; 1.0327x over previous
#include <cuda_runtime.h>

// PIF integrate-and-fire, closed form:
//   spikes = clamp(floor(x + 0.5f), 0, 8)   (bit-exact vs the T=8 scan)
//
// HBM-bound streaming pass: 205.5 MB in + 205.5 MB out.
// R2: 4 independent block-interleaved float4 loads per thread (MLP=4) +
// streaming cache hints (zero reuse -> evict-first, keep L2 out of the way).

__device__ __forceinline__ float4 pif4(float4 v) {
    float4 r;
    r.x = fminf(fmaxf(floorf(v.x + 0.5f), 0.0f), 8.0f);
    r.y = fminf(fmaxf(floorf(v.y + 0.5f), 0.0f), 8.0f);
    r.z = fminf(fmaxf(floorf(v.z + 0.5f), 0.0f), 8.0f);
    r.w = fminf(fmaxf(floorf(v.w + 0.5f), 0.0f), 8.0f);
    return r;
}

__global__ void __launch_bounds__(256) pif_kernel4(const float4* __restrict__ x,
                                                   float4* __restrict__ out,
                                                   int n4) {
    // Block-interleaved: each block owns a contiguous 1024-float4 tile;
    // each of its 4 loads is a fully coalesced warp access.
    int base = blockIdx.x * (256 * 4) + threadIdx.x;

    if (base + 3 * 256 < n4) {
        // Front-batched independent loads -> MLP_p1 = 4
        float4 a = __ldcs(x + base);
        float4 b = __ldcs(x + base + 256);
        float4 c = __ldcs(x + base + 512);
        float4 d = __ldcs(x + base + 768);
        __stcs(out + base,       pif4(a));
        __stcs(out + base + 256, pif4(b));
        __stcs(out + base + 512, pif4(c));
        __stcs(out + base + 768, pif4(d));
    } else {
        #pragma unroll
        for (int k = 0; k < 4; k++) {
            int i = base + k * 256;
            if (i < n4) __stcs(out + i, pif4(__ldcs(x + i)));
        }
    }
}

// Tail for element counts not divisible by 4 (not hit for this shape).
__global__ void pif_tail_kernel(const float* __restrict__ x,
                                float* __restrict__ out,
                                int start, int n) {
    int i = start + blockIdx.x * blockDim.x + threadIdx.x;
    if (i < n) {
        out[i] = fminf(fmaxf(floorf(x[i] + 0.5f), 0.0f), 8.0f);
    }
}

extern "C" void kernel_launch(void* const* d_in, const int* in_sizes, int n_in,
                              void* d_out, int out_size) {
    const float* x = (const float*)d_in[0];
    float* out = (float*)d_out;
    int n = in_sizes[0];

    int n4 = n / 4;
    if (n4 > 0) {
        const int per_block = 256 * 4;
        int blocks = (n4 + per_block - 1) / per_block;
        pif_kernel4<<<blocks, 256>>>((const float4*)x, (float4*)out, n4);
    }
    int rem_start = n4 * 4;
    if (rem_start < n) {
        int rem = n - rem_start;
        pif_tail_kernel<<<(rem + 255) / 256, 256>>>(x, out, rem_start, rem);
    }
}

// round 3
// speedup vs baseline: 1.0342x; 1.0015x over previous
#include <cuda_runtime.h>

// PIF integrate-and-fire, closed form:
//   spikes = clamp(floor(x + 0.5f), 0, 8)   (bit-exact vs the T=8 scan)
//
// HBM-bound streaming pass: 205.5 MB in + 205.5 MB out.
// R3: 8 independent block-interleaved float4 loads per thread (MLP_p1=8),
// streaming cache hints, and a branch-free main kernel (grid exactly tiles
// the full-tile region; ragged edge handled by a tiny second launch).

#define TPB 256
#define VPT 8                      // float4s per thread
#define TILE (TPB * VPT)           // float4s per block = 2048

__device__ __forceinline__ float4 pif4(float4 v) {
    float4 r;
    r.x = fminf(fmaxf(floorf(v.x + 0.5f), 0.0f), 8.0f);
    r.y = fminf(fmaxf(floorf(v.y + 0.5f), 0.0f), 8.0f);
    r.z = fminf(fmaxf(floorf(v.z + 0.5f), 0.0f), 8.0f);
    r.w = fminf(fmaxf(floorf(v.w + 0.5f), 0.0f), 8.0f);
    return r;
}

// Full tiles only — no bounds checks at all.
__global__ void __launch_bounds__(TPB) pif_kernel8(const float4* __restrict__ x,
                                                   float4* __restrict__ out) {
    int base = blockIdx.x * TILE + threadIdx.x;

    float4 v[VPT];
    #pragma unroll
    for (int k = 0; k < VPT; k++)          // front-batched: 8 independent LDG.128
        v[k] = __ldcs(x + base + k * TPB);
    #pragma unroll
    for (int k = 0; k < VPT; k++)
        __stcs(out + base + k * TPB, pif4(v[k]));
}

// Ragged edge (float4 granularity).
__global__ void pif_edge4(const float4* __restrict__ x, float4* __restrict__ out,
                          int start, int n4) {
    int i = start + blockIdx.x * blockDim.x + threadIdx.x;
    if (i < n4) __stcs(out + i, pif4(__ldcs(x + i)));
}

// Ragged edge (scalar granularity).
__global__ void pif_tail_kernel(const float* __restrict__ x, float* __restrict__ out,
                                int start, int n) {
    int i = start + blockIdx.x * blockDim.x + threadIdx.x;
    if (i < n) out[i] = fminf(fmaxf(floorf(x[i] + 0.5f), 0.0f), 8.0f);
}

extern "C" void kernel_launch(void* const* d_in, const int* in_sizes, int n_in,
                              void* d_out, int out_size) {
    const float* x = (const float*)d_in[0];
    float* out = (float*)d_out;
    int n = in_sizes[0];

    int n4 = n / 4;
    int full_blocks = n4 / TILE;                 // exact-fit, branch-free region
    if (full_blocks > 0) {
        pif_kernel8<<<full_blocks, TPB>>>((const float4*)x, (float4*)out);
    }
    int done4 = full_blocks * TILE;
    if (done4 < n4) {                            // leftover float4s
        int rem = n4 - done4;
        pif_edge4<<<(rem + TPB - 1) / TPB, TPB>>>((const float4*)x, (float4*)out,
                                                  done4, n4);
    }
    int rem_start = n4 * 4;
    if (rem_start < n) {                         // leftover scalars
        int rem = n - rem_start;
        pif_tail_kernel<<<(rem + TPB - 1) / TPB, TPB>>>(x, out, rem_start, rem);
    }
}